// round 2
// baseline (speedup 1.0000x reference)
#include <cuda_runtime.h>
#include <math_constants.h>
#include <cstdint>

// Problem constants
#define N_ROWS   65536      // 16*64*64
#define KDIM     8192       // num embeddings
#define DDIM     256        // embedding dim
#define QELEMS   16777216   // N_ROWS * DDIM
#define GATHER_BLOCKS 16384 // QELEMS / 4 / 256

// Scratch (no allocations allowed)
__device__ float  g_s1[N_ROWS];     // ||x_n||^2 (correctly-rounded fp32)
__device__ float  g_s2[KDIM];       // ||e_k||^2 (correctly-rounded fp32)
__device__ int    g_idx[N_ROWS];
__device__ double g_partials[GATHER_BLOCKS];

// ---------------------------------------------------------------------------
// Kernel 1: correctly-rounded fp32 row sums of squares for both x and emb.
// One warp per row; accumulate in double, round once to fp32.
// Warps [0, KDIM)           -> g_s2 from emb
// Warps [KDIM, KDIM+N_ROWS) -> g_s1 from x
// ---------------------------------------------------------------------------
__global__ void sums_kernel(const float* __restrict__ x,
                            const float* __restrict__ emb) {
    int warp = (blockIdx.x * blockDim.x + threadIdx.x) >> 5;
    int lane = threadIdx.x & 31;
    const float* row;
    float* dst;
    if (warp < KDIM) {
        row = emb + (size_t)warp * DDIM;
        dst = &g_s2[warp];
    } else if (warp < KDIM + N_ROWS) {
        row = x + (size_t)(warp - KDIM) * DDIM;
        dst = &g_s1[warp - KDIM];
    } else {
        return;
    }
    double s = 0.0;
#pragma unroll
    for (int i = 0; i < 8; i++) {
        double v = (double)row[lane + 32 * i];
        s = fma(v, v, s);
    }
#pragma unroll
    for (int m = 16; m; m >>= 1) s += __shfl_xor_sync(0xFFFFFFFFu, s, m);
    if (lane == 0) *dst = (float)s;
}

// ---------------------------------------------------------------------------
// Kernel 2: fused GEMM + argmin, replicating the reference's fp32 rounding:
//   d = fl32( fl32(s1 + s2) - 2*dot )   (fmaf(-2,dot,c) == single rounding)
// argmin with ties -> lowest index (jnp.argmin semantics).
// Block: 128 rows of x, loops over all 64 codebook tiles of 128 entries.
// 256 threads = 16x16; each thread owns an 8x8 micro-tile.
// ---------------------------------------------------------------------------
__global__ __launch_bounds__(256, 2)
void argmin_kernel(const float* __restrict__ x, const float* __restrict__ emb) {
    __shared__ float xs[16][132];   // [d][row], padded
    __shared__ float es[16][132];   // [d][col]
    __shared__ float e2s[128];

    const int tid = threadIdx.x;
    const int tx = tid & 15;        // column group
    const int ty = tid >> 4;        // row group
    const int rowBase = blockIdx.x * 128;

    float s1r[8];
#pragma unroll
    for (int i = 0; i < 8; i++) s1r[i] = g_s1[rowBase + ty * 8 + i];

    float best[8];
    int   bidx[8];
#pragma unroll
    for (int i = 0; i < 8; i++) { best[i] = CUDART_INF_F; bidx[i] = 0; }

    const float4* x4 = (const float4*)(x + (size_t)rowBase * DDIM);

    for (int kt = 0; kt < KDIM; kt += 128) {
        float acc[8][8];
#pragma unroll
        for (int i = 0; i < 8; i++)
#pragma unroll
            for (int j = 0; j < 8; j++) acc[i][j] = 0.f;

        const float4* e4 = (const float4*)(emb + (size_t)kt * DDIM);

        for (int d0 = 0; d0 < DDIM; d0 += 16) {
            __syncthreads();
#pragma unroll
            for (int p = 0; p < 2; p++) {
                int lin = tid + p * 256;
                int r = lin >> 2;
                int q = lin & 3;
                float4 v = x4[(size_t)r * 64 + (d0 >> 2) + q];
                xs[4 * q + 0][r] = v.x;
                xs[4 * q + 1][r] = v.y;
                xs[4 * q + 2][r] = v.z;
                xs[4 * q + 3][r] = v.w;
                float4 w = e4[(size_t)r * 64 + (d0 >> 2) + q];
                es[4 * q + 0][r] = w.x;
                es[4 * q + 1][r] = w.y;
                es[4 * q + 2][r] = w.z;
                es[4 * q + 3][r] = w.w;
            }
            if (d0 == 0 && tid < 128) e2s[tid] = g_s2[kt + tid];
            __syncthreads();

#pragma unroll
            for (int dd = 0; dd < 16; dd++) {
                float a[8], b[8];
#pragma unroll
                for (int i = 0; i < 8; i++) a[i] = xs[dd][ty * 8 + i];
#pragma unroll
                for (int j = 0; j < 8; j++) b[j] = es[dd][tx + 16 * j];
#pragma unroll
                for (int i = 0; i < 8; i++)
#pragma unroll
                    for (int j = 0; j < 8; j++)
                        acc[i][j] = fmaf(a[i], b[j], acc[i][j]);
            }
        }

        // Fold with reference-identical rounding.
#pragma unroll
        for (int j = 0; j < 8; j++) {
            int col = kt + tx + 16 * j;
            float s2v = e2s[tx + 16 * j];
#pragma unroll
            for (int i = 0; i < 8; i++) {
                float c = s1r[i] + s2v;               // fl32(s1 + s2)
                float d = fmaf(-2.f, acc[i][j], c);   // fl32(c - 2*dot)
                if (d < best[i] || (d == best[i] && col < bidx[i])) {
                    best[i] = d;
                    bidx[i] = col;
                }
            }
        }
    }

    // Final reduction across the 16 tx lanes sharing each row (within warp).
#pragma unroll
    for (int i = 0; i < 8; i++) {
        float v = best[i];
        int ix = bidx[i];
#pragma unroll
        for (int m = 8; m; m >>= 1) {
            float v2 = __shfl_xor_sync(0xFFFFFFFFu, v, m);
            int i2   = __shfl_xor_sync(0xFFFFFFFFu, ix, m);
            if (v2 < v || (v2 == v && i2 < ix)) { v = v2; ix = i2; }
        }
        if (tx == 0) g_idx[rowBase + ty * 8 + i] = ix;
    }
}

// ---------------------------------------------------------------------------
// Kernel 3: gather quantized, write quantized_st = x + (q - x),
// and per-block partial sums of (q - x)^2 (fp32 squares, double accumulation).
// ---------------------------------------------------------------------------
__global__ void gather_kernel(const float* __restrict__ x,
                              const float* __restrict__ emb,
                              float* __restrict__ out) {
    __shared__ double sred[256];
    const int tid = threadIdx.x;
    const size_t gid = (size_t)blockIdx.x * 256 + tid;   // float4 index
    const int row = (int)(gid >> 6);                     // 64 float4 per row
    const int q   = (int)(gid & 63);
    const int idx = g_idx[row];

    float4 xv = ((const float4*)x)[gid];
    float4 ev = ((const float4*)emb)[(size_t)idx * 64 + q];

    float4 o;
    o.x = xv.x + (ev.x - xv.x);
    o.y = xv.y + (ev.y - xv.y);
    o.z = xv.z + (ev.z - xv.z);
    o.w = xv.w + (ev.w - xv.w);
    ((float4*)out)[gid] = o;

    float dx = ev.x - xv.x;
    float dy = ev.y - xv.y;
    float dz = ev.z - xv.z;
    float dw = ev.w - xv.w;
    double s = (double)(dx * dx) + (double)(dy * dy)
             + (double)(dz * dz) + (double)(dw * dw);

    sred[tid] = s;
    __syncthreads();
#pragma unroll
    for (int m = 128; m; m >>= 1) {
        if (tid < m) sred[tid] += sred[tid + m];
        __syncthreads();
    }
    if (tid == 0) g_partials[blockIdx.x] = sred[0];
}

// ---------------------------------------------------------------------------
// Kernel 4: deterministic final loss reduction. loss = 1.25 * mean((q-x)^2).
// ---------------------------------------------------------------------------
__global__ void loss_kernel(float* __restrict__ out) {
    __shared__ double sred[256];
    const int tid = threadIdx.x;
    double s = 0.0;
    for (int i = tid; i < GATHER_BLOCKS; i += 256) s += g_partials[i];
    sred[tid] = s;
    __syncthreads();
#pragma unroll
    for (int m = 128; m; m >>= 1) {
        if (tid < m) sred[tid] += sred[tid + m];
        __syncthreads();
    }
    if (tid == 0) out[QELEMS] = (float)(1.25 * (sred[0] / (double)QELEMS));
}

// ---------------------------------------------------------------------------
// Kernel 5: indices as float into the tail of the output.
// ---------------------------------------------------------------------------
__global__ void idx_out_kernel(float* __restrict__ out) {
    int i = blockIdx.x * 256 + threadIdx.x;
    if (i < N_ROWS) out[QELEMS + 1 + i] = (float)g_idx[i];
}

// ---------------------------------------------------------------------------
extern "C" void kernel_launch(void* const* d_in, const int* in_sizes, int n_in,
                              void* d_out, int out_size) {
    const float* x   = (const float*)d_in[0];
    const float* emb = (const float*)d_in[1];
    if (n_in >= 2 && in_sizes[0] == KDIM * DDIM && in_sizes[1] == QELEMS) {
        emb = (const float*)d_in[0];
        x   = (const float*)d_in[1];
    }
    float* out = (float*)d_out;

    // (KDIM + N_ROWS) warps, 8 warps per block
    sums_kernel<<<(KDIM + N_ROWS) / 8, 256>>>(x, emb);
    argmin_kernel<<<N_ROWS / 128, 256>>>(x, emb);
    gather_kernel<<<GATHER_BLOCKS, 256>>>(x, emb, out);
    if (out_size >= QELEMS + 1) {
        loss_kernel<<<1, 256>>>(out);
    }
    if (out_size >= QELEMS + 1 + N_ROWS) {
        idx_out_kernel<<<(N_ROWS + 255) / 256, 256>>>(out);
    }
}

// round 4
// speedup vs baseline: 3.0174x; 3.0174x over previous
#include <cuda_runtime.h>
#include <cuda_bf16.h>
#include <math_constants.h>
#include <cstdint>

// Problem constants
#define N_ROWS   65536      // 16*64*64
#define KDIM     8192       // num embeddings
#define DDIM     256        // embedding dim
#define QELEMS   16777216   // N_ROWS * DDIM
#define GATHER_BLOCKS 16384 // QELEMS / 4 / 256
#define CAND_CAP 32
#define D_MARGIN 1e-4f

// ---------------------------------------------------------------------------
// Scratch (static device memory; no allocations allowed)
// ---------------------------------------------------------------------------
__device__ float          g_s1[N_ROWS];
__device__ float          g_s2[KDIM];
__device__ int            g_idx[N_ROWS];
__device__ double         g_partials[GATHER_BLOCKS];
__device__ __nv_bfloat16  g_xhi[QELEMS];
__device__ __nv_bfloat16  g_xlo[QELEMS];
__device__ __nv_bfloat16  g_ehi[KDIM * DDIM];
__device__ __nv_bfloat16  g_elo[KDIM * DDIM];
__device__ int            g_cand[(size_t)N_ROWS * CAND_CAP];
__device__ int            g_candcnt[N_ROWS];

// ---------------------------------------------------------------------------
// Helpers
// ---------------------------------------------------------------------------
__device__ __forceinline__ uint32_t smem_to_u32(const void* p) {
    uint32_t a;
    asm("{ .reg .u64 t; cvta.to.shared.u64 t, %1; cvt.u32.u64 %0, t; }"
        : "=r"(a) : "l"(p));
    return a;
}
#define SMEM_SWIZZLE_128B(off) ((off) ^ (((off) >> 3) & 0x70))

__device__ __forceinline__ void cp_async16(uint32_t dst, const void* src) {
    asm volatile("cp.async.cg.shared.global [%0], [%1], 16;" :: "r"(dst), "l"(src) : "memory");
}
#define CP_COMMIT() asm volatile("cp.async.commit_group;" ::: "memory")
#define CP_WAIT1()  asm volatile("cp.async.wait_group 1;" ::: "memory")

__device__ __forceinline__ void ldsm4(uint32_t* r, uint32_t addr) {
    asm volatile("ldmatrix.sync.aligned.m8n8.x4.shared.b16 {%0,%1,%2,%3}, [%4];"
                 : "=r"(r[0]), "=r"(r[1]), "=r"(r[2]), "=r"(r[3]) : "r"(addr));
}
__device__ __forceinline__ void mma16816(float* c, const uint32_t* a, const uint32_t* b) {
    asm volatile(
        "mma.sync.aligned.m16n8k16.row.col.f32.bf16.bf16.f32 "
        "{%0,%1,%2,%3}, {%4,%5,%6,%7}, {%8,%9}, {%0,%1,%2,%3};"
        : "+f"(c[0]), "+f"(c[1]), "+f"(c[2]), "+f"(c[3])
        : "r"(a[0]), "r"(a[1]), "r"(a[2]), "r"(a[3]), "r"(b[0]), "r"(b[1]));
}

// ---------------------------------------------------------------------------
// SMEM layout (dynamic, bytes)
// ---------------------------------------------------------------------------
#define SM_XHI    0          // 4 chunks x 16384
#define SM_XLO    65536      // 4 chunks x 16384
#define SM_EBUF   131072     // 2 bufs x (Ehi 16384 + Elo 16384)
#define SM_S2S    196608     // 2 x 128 floats
#define SM_S1S    197632     // 128 floats
#define SM_RBEST  198144     // 128 floats
#define SM_CAND2  198656     // 128 x 2 floats
#define SM_CNT    199680     // 128 ints
#define SMEM_TOTAL 200192

// ---------------------------------------------------------------------------
// Kernel 0: split x/emb into bf16 hi + lo residual.
// ---------------------------------------------------------------------------
__global__ void split_kernel(const float* __restrict__ x, const float* __restrict__ emb) {
    size_t i = (size_t)blockIdx.x * 256 + threadIdx.x;  // float4 index
    const float4* src;
    __nv_bfloat16 *hi, *lo;
    size_t base;
    if (i < QELEMS / 4) {
        src = (const float4*)x; hi = g_xhi; lo = g_xlo; base = i;
    } else {
        src = (const float4*)emb; hi = g_ehi; lo = g_elo; base = i - QELEMS / 4;
    }
    float4 v = src[base];
    __nv_bfloat16 h0 = __float2bfloat16(v.x);
    __nv_bfloat16 h1 = __float2bfloat16(v.y);
    __nv_bfloat16 h2 = __float2bfloat16(v.z);
    __nv_bfloat16 h3 = __float2bfloat16(v.w);
    __nv_bfloat16 l0 = __float2bfloat16(v.x - __bfloat162float(h0));
    __nv_bfloat16 l1 = __float2bfloat16(v.y - __bfloat162float(h1));
    __nv_bfloat16 l2 = __float2bfloat16(v.z - __bfloat162float(h2));
    __nv_bfloat16 l3 = __float2bfloat16(v.w - __bfloat162float(h3));
    ushort4 hv, lv;
    hv.x = *(unsigned short*)&h0; hv.y = *(unsigned short*)&h1;
    hv.z = *(unsigned short*)&h2; hv.w = *(unsigned short*)&h3;
    lv.x = *(unsigned short*)&l0; lv.y = *(unsigned short*)&l1;
    lv.z = *(unsigned short*)&l2; lv.w = *(unsigned short*)&l3;
    ((ushort4*)hi)[base] = hv;
    ((ushort4*)lo)[base] = lv;
}

// ---------------------------------------------------------------------------
// Kernel 1: correctly-rounded fp32 row sums of squares (double accumulate).
// ---------------------------------------------------------------------------
__global__ void sums_kernel(const float* __restrict__ x,
                            const float* __restrict__ emb) {
    int warp = (blockIdx.x * blockDim.x + threadIdx.x) >> 5;
    int lane = threadIdx.x & 31;
    const float* row;
    float* dst;
    if (warp < KDIM) {
        row = emb + (size_t)warp * DDIM;  dst = &g_s2[warp];
    } else if (warp < KDIM + N_ROWS) {
        row = x + (size_t)(warp - KDIM) * DDIM;  dst = &g_s1[warp - KDIM];
    } else return;
    double s = 0.0;
#pragma unroll
    for (int i = 0; i < 8; i++) {
        double v = (double)row[lane + 32 * i];
        s = fma(v, v, s);
    }
#pragma unroll
    for (int m = 16; m; m >>= 1) s += __shfl_xor_sync(0xFFFFFFFFu, s, m);
    if (lane == 0) *dst = (float)s;
}

// ---------------------------------------------------------------------------
// E-chunk prefetch (chunk id g2 in [0,256): tile t2=g2>>2, chunk c2=g2&3)
// ---------------------------------------------------------------------------
__device__ __forceinline__ void issue_e(uint32_t sb, int tid, int g2) {
    const int t2 = g2 >> 2, c2 = g2 & 3, b2 = g2 & 1, kt2 = t2 << 7;
#pragma unroll
    for (int j = 0; j < 8; j++) {
        int s = tid + j * 256;
        int m = s >> 10, rem = s & 1023, r = rem >> 3, seg = rem & 7;
        const __nv_bfloat16* src = (m ? g_elo : g_ehi)
            + (size_t)(kt2 + r) * DDIM + c2 * 64 + seg * 8;
        uint32_t dst = sb + SM_EBUF + b2 * 32768 + m * 16384
                     + SMEM_SWIZZLE_128B(r * 128 + seg * 16);
        cp_async16(dst, src);
    }
    if (c2 == 0 && tid < 32)
        cp_async16(sb + SM_S2S + (t2 & 1) * 512 + tid * 16, g_s2 + kt2 + tid * 4);
}

// ---------------------------------------------------------------------------
// Kernel 2: mma.sync bf16x3 GEMM + approx argmin + candidate collection.
// CTA: 128 rows x 128-code tiles (64 tiles), K chunked by 64.
// 8 warps: warp w -> rows [ (w>>1)*32, +32 ), cols [ (w&1)*64, +64 ).
// ---------------------------------------------------------------------------
__global__ __launch_bounds__(256, 1)
void vq_mma_kernel() {
    extern __shared__ char smem[];
    const uint32_t sb = smem_to_u32(smem);
    const int tid  = threadIdx.x;
    const int wid  = tid >> 5;
    const int lane = tid & 31;
    const int wy = wid >> 1, wx = wid & 1;
    const int g4 = lane >> 2, t4 = lane & 3;
    const int rowBase = blockIdx.x * 128;

    float* s1p    = (float*)(smem + SM_S1S);
    float* rbestS = (float*)(smem + SM_RBEST);
    float* cand2  = (float*)(smem + SM_CAND2);
    int*   cnt    = (int*)(smem + SM_CNT);

    if (tid < 128) {
        cnt[tid] = 0;
        s1p[tid] = g_s1[rowBase + tid];
    }

    // ---- X hi/lo (all 4 chunks) ----
#pragma unroll 4
    for (int it = 0; it < 32; it++) {
        int idx = it * 256 + tid;
        int m   = idx >> 12;
        int rem = idx & 4095;
        int r   = rem >> 5;
        int c   = (rem >> 3) & 3;
        int seg = rem & 7;
        const __nv_bfloat16* src = (m ? g_xlo : g_xhi)
            + (size_t)(rowBase + r) * DDIM + c * 64 + seg * 8;
        uint32_t dst = sb + (m ? SM_XLO : SM_XHI) + c * 16384
                     + SMEM_SWIZZLE_128B(r * 128 + seg * 16);
        cp_async16(dst, src);
    }
    CP_COMMIT();
    issue_e(sb, tid, 0); CP_COMMIT();
    issue_e(sb, tid, 1); CP_COMMIT();

    float rbest_reg = CUDART_INF_F;
    float acc[2][8][4];

    // Precomputed ldmatrix address components
    const uint32_t a_row  = (uint32_t)(wy * 32 + (lane & 15));
    const uint32_t a_koff = (uint32_t)(((lane >> 4) & 1) * 16);
    const uint32_t b_nrow = (uint32_t)(wx * 64 + (lane & 7) + ((lane >> 4) & 1) * 8);
    const uint32_t b_koff = (uint32_t)(((lane >> 3) & 1) * 16);

#pragma unroll 1
    for (int g = 0; g < 256; g++) {
        const int t = g >> 2, c = g & 3, b = g & 1, kt = t << 7;

        if (c == 0) {
#pragma unroll
            for (int mi = 0; mi < 2; mi++)
#pragma unroll
                for (int ni = 0; ni < 8; ni++)
#pragma unroll
                    for (int e = 0; e < 4; e++) acc[mi][ni][e] = 0.f;
        }

        CP_WAIT1();
        __syncthreads();

        const uint32_t xh = sb + SM_XHI + c * 16384;
        const uint32_t xl = sb + SM_XLO + c * 16384;
        const uint32_t eh = sb + SM_EBUF + b * 32768;
        const uint32_t el = eh + 16384;

#pragma unroll
        for (int ks = 0; ks < 4; ks++) {
            uint32_t ahi[2][4], alo[2][4];
#pragma unroll
            for (int mi = 0; mi < 2; mi++) {
                uint32_t off = (a_row + mi * 16) * 128 + ks * 32 + a_koff;
                uint32_t sw  = SMEM_SWIZZLE_128B(off);
                ldsm4(ahi[mi], xh + sw);
                ldsm4(alo[mi], xl + sw);
            }
            uint32_t bh[8][2], bl[8][2];
#pragma unroll
            for (int nq = 0; nq < 4; nq++) {
                uint32_t off = (b_nrow + nq * 16) * 128 + ks * 32 + b_koff;
                uint32_t sw  = SMEM_SWIZZLE_128B(off);
                uint32_t r4[4];
                ldsm4(r4, eh + sw);
                bh[2 * nq][0] = r4[0]; bh[2 * nq][1] = r4[1];
                bh[2 * nq + 1][0] = r4[2]; bh[2 * nq + 1][1] = r4[3];
                ldsm4(r4, el + sw);
                bl[2 * nq][0] = r4[0]; bl[2 * nq][1] = r4[1];
                bl[2 * nq + 1][0] = r4[2]; bl[2 * nq + 1][1] = r4[3];
            }
#pragma unroll
            for (int mi = 0; mi < 2; mi++)
#pragma unroll
                for (int ni = 0; ni < 8; ni++) {
                    mma16816(acc[mi][ni], ahi[mi], bh[ni]);
                    mma16816(acc[mi][ni], ahi[mi], bl[ni]);
                    mma16816(acc[mi][ni], alo[mi], bh[ni]);
                }
        }

        if (c == 3) {
            const float* s2p = (const float*)(smem + SM_S2S) + (t & 1) * 128;
            // Pass A: per-thread row minima -> warp -> cand2
            float pmin[4] = {CUDART_INF_F, CUDART_INF_F, CUDART_INF_F, CUDART_INF_F};
#pragma unroll
            for (int mi = 0; mi < 2; mi++)
#pragma unroll
                for (int ni = 0; ni < 8; ni++)
#pragma unroll
                    for (int e = 0; e < 4; e++) {
                        int rl = wy * 32 + mi * 16 + g4 + ((e >> 1) << 3);
                        int cl = wx * 64 + ni * 8 + 2 * t4 + (e & 1);
                        float d = fmaf(-2.f, acc[mi][ni][e], s1p[rl] + s2p[cl]);
                        int pi = mi * 2 + (e >> 1);
                        pmin[pi] = fminf(pmin[pi], d);
                    }
#pragma unroll
            for (int pi = 0; pi < 4; pi++) {
                pmin[pi] = fminf(pmin[pi], __shfl_xor_sync(0xFFFFFFFFu, pmin[pi], 1));
                pmin[pi] = fminf(pmin[pi], __shfl_xor_sync(0xFFFFFFFFu, pmin[pi], 2));
            }
            if (t4 == 0) {
#pragma unroll
                for (int pi = 0; pi < 4; pi++) {
                    int rl = wy * 32 + (pi >> 1) * 16 + g4 + ((pi & 1) << 3);
                    cand2[rl * 2 + wx] = pmin[pi];
                }
            }
            __syncthreads();
            if (tid < 128) {
                float m = fminf(cand2[tid * 2], cand2[tid * 2 + 1]);
                rbest_reg = fminf(rbest_reg, m);
                rbestS[tid] = rbest_reg;
            }
            __syncthreads();
            // Pass B: collect candidates within margin of running min
#pragma unroll
            for (int mi = 0; mi < 2; mi++)
#pragma unroll
                for (int ni = 0; ni < 8; ni++)
#pragma unroll
                    for (int e = 0; e < 4; e++) {
                        int rl = wy * 32 + mi * 16 + g4 + ((e >> 1) << 3);
                        int cl = wx * 64 + ni * 8 + 2 * t4 + (e & 1);
                        float d = fmaf(-2.f, acc[mi][ni][e], s1p[rl] + s2p[cl]);
                        if (d <= rbestS[rl] + D_MARGIN) {
                            int slot = atomicAdd(&cnt[rl], 1);
                            if (slot < CAND_CAP)
                                g_cand[(size_t)(rowBase + rl) * CAND_CAP + slot] = kt + cl;
                        }
                    }
        }

        __syncthreads();
        if (g + 2 < 256) { issue_e(sb, tid, g + 2); CP_COMMIT(); }
    }

    __syncthreads();
    if (tid < 128) {
        int n = cnt[tid];
        g_candcnt[rowBase + tid] = (n < CAND_CAP) ? n : CAND_CAP;
    }
}

// ---------------------------------------------------------------------------
// Kernel 3: exact rescore of candidates (double dot -> fp32 -> ref rounding).
// One warp per row.
// ---------------------------------------------------------------------------
__global__ void rescore_kernel(const float* __restrict__ x,
                               const float* __restrict__ emb) {
    int warp = (blockIdx.x * blockDim.x + threadIdx.x) >> 5;
    int lane = threadIdx.x & 31;
    if (warp >= N_ROWS) return;
    int n = g_candcnt[warp];

    const float4* xr = (const float4*)(x + (size_t)warp * DDIM);
    float4 xv0 = xr[lane * 2], xv1 = xr[lane * 2 + 1];
    float s1 = g_s1[warp];

    float best = CUDART_INF_F;
    int   bidx = 0;
    for (int i = 0; i < n; i++) {
        int cIdx = g_cand[(size_t)warp * CAND_CAP + i];
        const float4* er = (const float4*)(emb + (size_t)cIdx * DDIM);
        float4 e0 = er[lane * 2], e1 = er[lane * 2 + 1];
        double dot = 0.0;
        dot = fma((double)xv0.x, (double)e0.x, dot);
        dot = fma((double)xv0.y, (double)e0.y, dot);
        dot = fma((double)xv0.z, (double)e0.z, dot);
        dot = fma((double)xv0.w, (double)e0.w, dot);
        dot = fma((double)xv1.x, (double)e1.x, dot);
        dot = fma((double)xv1.y, (double)e1.y, dot);
        dot = fma((double)xv1.z, (double)e1.z, dot);
        dot = fma((double)xv1.w, (double)e1.w, dot);
#pragma unroll
        for (int m = 16; m; m >>= 1) dot += __shfl_xor_sync(0xFFFFFFFFu, dot, m);
        float dotf = (float)dot;
        float d = fmaf(-2.f, dotf, s1 + g_s2[cIdx]);
        if (d < best || (d == best && cIdx < bidx)) { best = d; bidx = cIdx; }
    }
    if (lane == 0) g_idx[warp] = (n > 0) ? bidx : 0;
}

// ---------------------------------------------------------------------------
// Kernel 4: gather quantized + per-block loss partials.
// ---------------------------------------------------------------------------
__global__ void gather_kernel(const float* __restrict__ x,
                              const float* __restrict__ emb,
                              float* __restrict__ out) {
    __shared__ double sred[256];
    const int tid = threadIdx.x;
    const size_t gid = (size_t)blockIdx.x * 256 + tid;
    const int row = (int)(gid >> 6);
    const int q   = (int)(gid & 63);
    const int idx = g_idx[row];

    float4 xv = ((const float4*)x)[gid];
    float4 ev = ((const float4*)emb)[(size_t)idx * 64 + q];

    float4 o;
    o.x = xv.x + (ev.x - xv.x);
    o.y = xv.y + (ev.y - xv.y);
    o.z = xv.z + (ev.z - xv.z);
    o.w = xv.w + (ev.w - xv.w);
    ((float4*)out)[gid] = o;

    float dx = ev.x - xv.x, dy = ev.y - xv.y, dz = ev.z - xv.z, dw = ev.w - xv.w;
    double s = (double)(dx * dx) + (double)(dy * dy)
             + (double)(dz * dz) + (double)(dw * dw);
    sred[tid] = s;
    __syncthreads();
#pragma unroll
    for (int m = 128; m; m >>= 1) {
        if (tid < m) sred[tid] += sred[tid + m];
        __syncthreads();
    }
    if (tid == 0) g_partials[blockIdx.x] = sred[0];
}

__global__ void loss_kernel(float* __restrict__ out) {
    __shared__ double sred[256];
    const int tid = threadIdx.x;
    double s = 0.0;
    for (int i = tid; i < GATHER_BLOCKS; i += 256) s += g_partials[i];
    sred[tid] = s;
    __syncthreads();
#pragma unroll
    for (int m = 128; m; m >>= 1) {
        if (tid < m) sred[tid] += sred[tid + m];
        __syncthreads();
    }
    if (tid == 0) out[QELEMS] = (float)(1.25 * (sred[0] / (double)QELEMS));
}

__global__ void idx_out_kernel(float* __restrict__ out) {
    int i = blockIdx.x * 256 + threadIdx.x;
    if (i < N_ROWS) out[QELEMS + 1 + i] = (float)g_idx[i];
}

// ---------------------------------------------------------------------------
extern "C" void kernel_launch(void* const* d_in, const int* in_sizes, int n_in,
                              void* d_out, int out_size) {
    const float* x   = (const float*)d_in[0];
    const float* emb = (const float*)d_in[1];
    if (n_in >= 2 && in_sizes[0] == KDIM * DDIM && in_sizes[1] == QELEMS) {
        emb = (const float*)d_in[0];
        x   = (const float*)d_in[1];
    }
    float* out = (float*)d_out;

    cudaFuncSetAttribute(vq_mma_kernel,
                         cudaFuncAttributeMaxDynamicSharedMemorySize, SMEM_TOTAL);

    split_kernel<<<(QELEMS / 4 + KDIM * DDIM / 4) / 256, 256>>>(x, emb);
    sums_kernel<<<(KDIM + N_ROWS) / 8, 256>>>(x, emb);
    vq_mma_kernel<<<N_ROWS / 128, 256, SMEM_TOTAL>>>();
    rescore_kernel<<<N_ROWS / 8, 256>>>(x, emb);
    gather_kernel<<<GATHER_BLOCKS, 256>>>(x, emb, out);
    if (out_size >= QELEMS + 1) {
        loss_kernel<<<1, 256>>>(out);
    }
    if (out_size >= QELEMS + 1 + N_ROWS) {
        idx_out_kernel<<<(N_ROWS + 255) / 256, 256>>>(out);
    }
}

// round 5
// speedup vs baseline: 7.5688x; 2.5084x over previous
#include <cuda_runtime.h>
#include <cuda_bf16.h>
#include <math_constants.h>
#include <cstdint>

// Problem constants
#define N_ROWS   65536      // 16*64*64
#define KDIM     8192       // num embeddings
#define DDIM     256        // embedding dim
#define QELEMS   16777216   // N_ROWS * DDIM
#define GATHER_BLOCKS 16384 // QELEMS / 4 / 256
#define CAND_CAP 32
#define D_MARGIN 8e-3f

// ---------------------------------------------------------------------------
// Scratch (static device memory; no allocations allowed)
// ---------------------------------------------------------------------------
__device__ float          g_s1[N_ROWS];
__device__ float          g_s2[KDIM];
__device__ int            g_idx[N_ROWS];
__device__ double         g_partials[GATHER_BLOCKS];
__device__ __nv_bfloat16  g_xhi[QELEMS];
__device__ __nv_bfloat16  g_ehi[KDIM * DDIM];
__device__ int            g_cand[(size_t)N_ROWS * CAND_CAP];
__device__ int            g_candcnt[N_ROWS];

// ---------------------------------------------------------------------------
// Helpers
// ---------------------------------------------------------------------------
__device__ __forceinline__ uint32_t smem_to_u32(const void* p) {
    uint32_t a;
    asm("{ .reg .u64 t; cvta.to.shared.u64 t, %1; cvt.u32.u64 %0, t; }"
        : "=r"(a) : "l"(p));
    return a;
}
#define SMEM_SWIZZLE_128B(off) ((off) ^ (((off) >> 3) & 0x70))

__device__ __forceinline__ void cp_async16(uint32_t dst, const void* src) {
    asm volatile("cp.async.cg.shared.global [%0], [%1], 16;" :: "r"(dst), "l"(src) : "memory");
}
#define CP_COMMIT() asm volatile("cp.async.commit_group;" ::: "memory")
#define CP_WAIT1()  asm volatile("cp.async.wait_group 1;" ::: "memory")

__device__ __forceinline__ void ldsm4(uint32_t* r, uint32_t addr) {
    asm volatile("ldmatrix.sync.aligned.m8n8.x4.shared.b16 {%0,%1,%2,%3}, [%4];"
                 : "=r"(r[0]), "=r"(r[1]), "=r"(r[2]), "=r"(r[3]) : "r"(addr));
}
__device__ __forceinline__ void mma16816(float* c, const uint32_t* a, const uint32_t* b) {
    asm volatile(
        "mma.sync.aligned.m16n8k16.row.col.f32.bf16.bf16.f32 "
        "{%0,%1,%2,%3}, {%4,%5,%6,%7}, {%8,%9}, {%0,%1,%2,%3};"
        : "+f"(c[0]), "+f"(c[1]), "+f"(c[2]), "+f"(c[3])
        : "r"(a[0]), "r"(a[1]), "r"(a[2]), "r"(a[3]), "r"(b[0]), "r"(b[1]));
}

// ---------------------------------------------------------------------------
// SMEM layout (dynamic, bytes)
// ---------------------------------------------------------------------------
#define SM_XHI    0          // 4 chunks x 16384
#define SM_EBUF   65536      // 2 bufs x 16384
#define SM_S2S    98304      // 2 x 128 floats
#define SM_S1S    99328      // 128 floats
#define SM_RBEST  99840      // 128 floats
#define SM_CAND2  100352     // 128 x 2 floats
#define SM_CNT    101376     // 128 ints
#define SMEM_TOTAL 101888

// ---------------------------------------------------------------------------
// Kernel 0: fused split (fp32 -> bf16 hi) + correctly-rounded row sum-of-squares.
// One warp per row. Warps [0,KDIM) -> emb, [KDIM, KDIM+N_ROWS) -> x.
// ---------------------------------------------------------------------------
__global__ void prep_kernel(const float* __restrict__ x,
                            const float* __restrict__ emb) {
    int warp = (blockIdx.x * blockDim.x + threadIdx.x) >> 5;
    int lane = threadIdx.x & 31;
    const float* row;
    float* sdst;
    __nv_bfloat16* hdst;
    if (warp < KDIM) {
        row  = emb + (size_t)warp * DDIM;
        sdst = &g_s2[warp];
        hdst = g_ehi + (size_t)warp * DDIM;
    } else if (warp < KDIM + N_ROWS) {
        int r = warp - KDIM;
        row  = x + (size_t)r * DDIM;
        sdst = &g_s1[r];
        hdst = g_xhi + (size_t)r * DDIM;
    } else return;

    const float4* r4 = (const float4*)row;
    float4 v0 = r4[lane * 2];
    float4 v1 = r4[lane * 2 + 1];

    // bf16 hi conversions
    __nv_bfloat16 h[8];
    h[0] = __float2bfloat16(v0.x); h[1] = __float2bfloat16(v0.y);
    h[2] = __float2bfloat16(v0.z); h[3] = __float2bfloat16(v0.w);
    h[4] = __float2bfloat16(v1.x); h[5] = __float2bfloat16(v1.y);
    h[6] = __float2bfloat16(v1.z); h[7] = __float2bfloat16(v1.w);
    uint4 pack;
    unsigned short* ps = (unsigned short*)&pack;
#pragma unroll
    for (int i = 0; i < 8; i++) ps[i] = *(unsigned short*)&h[i];
    ((uint4*)hdst)[lane] = pack;

    // double-precision sum of squares
    double s = 0.0;
    s = fma((double)v0.x, (double)v0.x, s);
    s = fma((double)v0.y, (double)v0.y, s);
    s = fma((double)v0.z, (double)v0.z, s);
    s = fma((double)v0.w, (double)v0.w, s);
    s = fma((double)v1.x, (double)v1.x, s);
    s = fma((double)v1.y, (double)v1.y, s);
    s = fma((double)v1.z, (double)v1.z, s);
    s = fma((double)v1.w, (double)v1.w, s);
#pragma unroll
    for (int m = 16; m; m >>= 1) s += __shfl_xor_sync(0xFFFFFFFFu, s, m);
    if (lane == 0) *sdst = (float)s;
}

// ---------------------------------------------------------------------------
// E-chunk prefetch (chunk id g2 in [0,256): tile t2=g2>>2, chunk c2=g2&3)
// ---------------------------------------------------------------------------
__device__ __forceinline__ void issue_e(uint32_t sb, int tid, int g2) {
    const int t2 = g2 >> 2, c2 = g2 & 3, b2 = g2 & 1, kt2 = t2 << 7;
#pragma unroll
    for (int j = 0; j < 4; j++) {
        int s = tid + j * 256;           // [0,1024)
        int r = s >> 3, seg = s & 7;
        const __nv_bfloat16* src = g_ehi
            + (size_t)(kt2 + r) * DDIM + c2 * 64 + seg * 8;
        uint32_t dst = sb + SM_EBUF + b2 * 16384
                     + SMEM_SWIZZLE_128B(r * 128 + seg * 16);
        cp_async16(dst, src);
    }
    if (c2 == 0 && tid < 32)
        cp_async16(sb + SM_S2S + (t2 & 1) * 512 + tid * 16, g_s2 + kt2 + tid * 4);
}

// ---------------------------------------------------------------------------
// Kernel 1: mma.sync bf16 (hi.hi only) GEMM + approx argmin + candidates.
// CTA: 128 rows x 128-code tiles (64 tiles), K chunked by 64.
// 8 warps: warp w -> rows [ (w>>1)*32, +32 ), cols [ (w&1)*64, +64 ).
// ---------------------------------------------------------------------------
__global__ __launch_bounds__(256, 2)
void vq_mma_kernel() {
    extern __shared__ char smem[];
    const uint32_t sb = smem_to_u32(smem);
    const int tid  = threadIdx.x;
    const int wid  = tid >> 5;
    const int lane = tid & 31;
    const int wy = wid >> 1, wx = wid & 1;
    const int g4 = lane >> 2, t4 = lane & 3;
    const int rowBase = blockIdx.x * 128;

    float* s1p    = (float*)(smem + SM_S1S);
    float* rbestS = (float*)(smem + SM_RBEST);
    float* cand2  = (float*)(smem + SM_CAND2);
    int*   cnt    = (int*)(smem + SM_CNT);

    if (tid < 128) {
        cnt[tid] = 0;
        s1p[tid] = g_s1[rowBase + tid];
    }

    // ---- X hi (4 chunks), 4096 x 16B segments ----
#pragma unroll 4
    for (int it = 0; it < 16; it++) {
        int idx = it * 256 + tid;        // [0,4096)
        int r   = idx >> 5;              // 0..127
        int c   = (idx >> 3) & 3;        // chunk
        int seg = idx & 7;
        const __nv_bfloat16* src = g_xhi
            + (size_t)(rowBase + r) * DDIM + c * 64 + seg * 8;
        uint32_t dst = sb + SM_XHI + c * 16384
                     + SMEM_SWIZZLE_128B(r * 128 + seg * 16);
        cp_async16(dst, src);
    }
    CP_COMMIT();
    issue_e(sb, tid, 0); CP_COMMIT();
    issue_e(sb, tid, 1); CP_COMMIT();

    float rbest_reg = CUDART_INF_F;
    float acc[2][8][4];

    // Precomputed ldmatrix address components
    const uint32_t a_row  = (uint32_t)(wy * 32 + (lane & 15));
    const uint32_t a_koff = (uint32_t)(((lane >> 4) & 1) * 16);
    const uint32_t b_nrow = (uint32_t)(wx * 64 + (lane & 7) + ((lane >> 4) & 1) * 8);
    const uint32_t b_koff = (uint32_t)(((lane >> 3) & 1) * 16);

#pragma unroll 1
    for (int g = 0; g < 256; g++) {
        const int t = g >> 2, c = g & 3, b = g & 1, kt = t << 7;

        if (c == 0) {
#pragma unroll
            for (int mi = 0; mi < 2; mi++)
#pragma unroll
                for (int ni = 0; ni < 8; ni++)
#pragma unroll
                    for (int e = 0; e < 4; e++) acc[mi][ni][e] = 0.f;
        }

        CP_WAIT1();
        __syncthreads();

        const uint32_t xh = sb + SM_XHI + c * 16384;
        const uint32_t eh = sb + SM_EBUF + b * 16384;

#pragma unroll
        for (int ks = 0; ks < 4; ks++) {
            uint32_t ahi[2][4];
#pragma unroll
            for (int mi = 0; mi < 2; mi++) {
                uint32_t off = (a_row + mi * 16) * 128 + ks * 32 + a_koff;
                ldsm4(ahi[mi], xh + SMEM_SWIZZLE_128B(off));
            }
            uint32_t bh[8][2];
#pragma unroll
            for (int nq = 0; nq < 4; nq++) {
                uint32_t off = (b_nrow + nq * 16) * 128 + ks * 32 + b_koff;
                uint32_t r4[4];
                ldsm4(r4, eh + SMEM_SWIZZLE_128B(off));
                bh[2 * nq][0] = r4[0]; bh[2 * nq][1] = r4[1];
                bh[2 * nq + 1][0] = r4[2]; bh[2 * nq + 1][1] = r4[3];
            }
#pragma unroll
            for (int mi = 0; mi < 2; mi++)
#pragma unroll
                for (int ni = 0; ni < 8; ni++)
                    mma16816(acc[mi][ni], ahi[mi], bh[ni]);
        }

        if (c == 3) {
            const float* s2p = (const float*)(smem + SM_S2S) + (t & 1) * 128;
            // Pass A: per-thread row minima -> warp -> cand2
            float pmin[4] = {CUDART_INF_F, CUDART_INF_F, CUDART_INF_F, CUDART_INF_F};
#pragma unroll
            for (int mi = 0; mi < 2; mi++)
#pragma unroll
                for (int ni = 0; ni < 8; ni++)
#pragma unroll
                    for (int e = 0; e < 4; e++) {
                        int rl = wy * 32 + mi * 16 + g4 + ((e >> 1) << 3);
                        int cl = wx * 64 + ni * 8 + 2 * t4 + (e & 1);
                        float d = fmaf(-2.f, acc[mi][ni][e], s1p[rl] + s2p[cl]);
                        int pi = mi * 2 + (e >> 1);
                        pmin[pi] = fminf(pmin[pi], d);
                    }
#pragma unroll
            for (int pi = 0; pi < 4; pi++) {
                pmin[pi] = fminf(pmin[pi], __shfl_xor_sync(0xFFFFFFFFu, pmin[pi], 1));
                pmin[pi] = fminf(pmin[pi], __shfl_xor_sync(0xFFFFFFFFu, pmin[pi], 2));
            }
            if (t4 == 0) {
#pragma unroll
                for (int pi = 0; pi < 4; pi++) {
                    int rl = wy * 32 + (pi >> 1) * 16 + g4 + ((pi & 1) << 3);
                    cand2[rl * 2 + wx] = pmin[pi];
                }
            }
            __syncthreads();
            if (tid < 128) {
                float m = fminf(cand2[tid * 2], cand2[tid * 2 + 1]);
                rbest_reg = fminf(rbest_reg, m);
                rbestS[tid] = rbest_reg;
            }
            __syncthreads();
            // Pass B: collect candidates within margin of running min
#pragma unroll
            for (int mi = 0; mi < 2; mi++)
#pragma unroll
                for (int ni = 0; ni < 8; ni++)
#pragma unroll
                    for (int e = 0; e < 4; e++) {
                        int rl = wy * 32 + mi * 16 + g4 + ((e >> 1) << 3);
                        int cl = wx * 64 + ni * 8 + 2 * t4 + (e & 1);
                        float d = fmaf(-2.f, acc[mi][ni][e], s1p[rl] + s2p[cl]);
                        if (d <= rbestS[rl] + D_MARGIN) {
                            int slot = atomicAdd(&cnt[rl], 1);
                            if (slot < CAND_CAP)
                                g_cand[(size_t)(rowBase + rl) * CAND_CAP + slot] = kt + cl;
                        }
                    }
        }

        __syncthreads();
        if (g + 2 < 256) { issue_e(sb, tid, g + 2); CP_COMMIT(); }
    }

    __syncthreads();
    if (tid < 128) {
        int n = cnt[tid];
        g_candcnt[rowBase + tid] = (n < CAND_CAP) ? n : CAND_CAP;
    }
}

// ---------------------------------------------------------------------------
// Kernel 2: exact rescore of candidates (double dot -> fp32 -> ref rounding).
// One warp per row.
// ---------------------------------------------------------------------------
__global__ void rescore_kernel(const float* __restrict__ x,
                               const float* __restrict__ emb) {
    int warp = (blockIdx.x * blockDim.x + threadIdx.x) >> 5;
    int lane = threadIdx.x & 31;
    if (warp >= N_ROWS) return;
    int n = g_candcnt[warp];

    const float4* xr = (const float4*)(x + (size_t)warp * DDIM);
    float4 xv0 = xr[lane * 2], xv1 = xr[lane * 2 + 1];
    float s1 = g_s1[warp];

    float best = CUDART_INF_F;
    int   bidx = 0;
    for (int i = 0; i < n; i++) {
        int cIdx = g_cand[(size_t)warp * CAND_CAP + i];
        const float4* er = (const float4*)(emb + (size_t)cIdx * DDIM);
        float4 e0 = er[lane * 2], e1 = er[lane * 2 + 1];
        double dot = 0.0;
        dot = fma((double)xv0.x, (double)e0.x, dot);
        dot = fma((double)xv0.y, (double)e0.y, dot);
        dot = fma((double)xv0.z, (double)e0.z, dot);
        dot = fma((double)xv0.w, (double)e0.w, dot);
        dot = fma((double)xv1.x, (double)e1.x, dot);
        dot = fma((double)xv1.y, (double)e1.y, dot);
        dot = fma((double)xv1.z, (double)e1.z, dot);
        dot = fma((double)xv1.w, (double)e1.w, dot);
#pragma unroll
        for (int m = 16; m; m >>= 1) dot += __shfl_xor_sync(0xFFFFFFFFu, dot, m);
        float dotf = (float)dot;
        float d = fmaf(-2.f, dotf, s1 + g_s2[cIdx]);
        if (d < best || (d == best && cIdx < bidx)) { best = d; bidx = cIdx; }
    }
    if (lane == 0) g_idx[warp] = (n > 0) ? bidx : 0;
}

// ---------------------------------------------------------------------------
// Kernel 3: gather quantized + per-block loss partials.
// ---------------------------------------------------------------------------
__global__ void gather_kernel(const float* __restrict__ x,
                              const float* __restrict__ emb,
                              float* __restrict__ out) {
    __shared__ double sred[256];
    const int tid = threadIdx.x;
    const size_t gid = (size_t)blockIdx.x * 256 + tid;
    const int row = (int)(gid >> 6);
    const int q   = (int)(gid & 63);
    const int idx = g_idx[row];

    float4 xv = ((const float4*)x)[gid];
    float4 ev = ((const float4*)emb)[(size_t)idx * 64 + q];

    float4 o;
    o.x = xv.x + (ev.x - xv.x);
    o.y = xv.y + (ev.y - xv.y);
    o.z = xv.z + (ev.z - xv.z);
    o.w = xv.w + (ev.w - xv.w);
    ((float4*)out)[gid] = o;

    float dx = ev.x - xv.x, dy = ev.y - xv.y, dz = ev.z - xv.z, dw = ev.w - xv.w;
    double s = (double)(dx * dx) + (double)(dy * dy)
             + (double)(dz * dz) + (double)(dw * dw);
    sred[tid] = s;
    __syncthreads();
#pragma unroll
    for (int m = 128; m; m >>= 1) {
        if (tid < m) sred[tid] += sred[tid + m];
        __syncthreads();
    }
    if (tid == 0) g_partials[blockIdx.x] = sred[0];
}

__global__ void loss_kernel(float* __restrict__ out) {
    __shared__ double sred[256];
    const int tid = threadIdx.x;
    double s = 0.0;
    for (int i = tid; i < GATHER_BLOCKS; i += 256) s += g_partials[i];
    sred[tid] = s;
    __syncthreads();
#pragma unroll
    for (int m = 128; m; m >>= 1) {
        if (tid < m) sred[tid] += sred[tid + m];
        __syncthreads();
    }
    if (tid == 0) out[QELEMS] = (float)(1.25 * (sred[0] / (double)QELEMS));
}

__global__ void idx_out_kernel(float* __restrict__ out) {
    int i = blockIdx.x * 256 + threadIdx.x;
    if (i < N_ROWS) out[QELEMS + 1 + i] = (float)g_idx[i];
}

// ---------------------------------------------------------------------------
extern "C" void kernel_launch(void* const* d_in, const int* in_sizes, int n_in,
                              void* d_out, int out_size) {
    const float* x   = (const float*)d_in[0];
    const float* emb = (const float*)d_in[1];
    if (n_in >= 2 && in_sizes[0] == KDIM * DDIM && in_sizes[1] == QELEMS) {
        emb = (const float*)d_in[0];
        x   = (const float*)d_in[1];
    }
    float* out = (float*)d_out;

    cudaFuncSetAttribute(vq_mma_kernel,
                         cudaFuncAttributeMaxDynamicSharedMemorySize, SMEM_TOTAL);

    prep_kernel<<<(KDIM + N_ROWS) / 8, 256>>>(x, emb);
    vq_mma_kernel<<<N_ROWS / 128, 256, SMEM_TOTAL>>>();
    rescore_kernel<<<N_ROWS / 8, 256>>>(x, emb);
    gather_kernel<<<GATHER_BLOCKS, 256>>>(x, emb, out);
    if (out_size >= QELEMS + 1) {
        loss_kernel<<<1, 256>>>(out);
    }
    if (out_size >= QELEMS + 1 + N_ROWS) {
        idx_out_kernel<<<(N_ROWS + 255) / 256, 256>>>(out);
    }
}